// round 5
// baseline (speedup 1.0000x reference)
#include <cuda_runtime.h>
#include <math.h>

// ---------------------------------------------------------------------------
// GCN_45921790329163
// R4: back to 512-thread LSTM CTAs (4 warps/SMSP). Inner loop restructured:
//     weights loaded as natural f32x2 pairs (no MOV broadcasts), inputs stored
//     pre-duplicated in smem -> 12 issues/k vs FMA floor 16 cyc/k.
// ---------------------------------------------------------------------------

#define DEV_INLINE __device__ __forceinline__

constexpr int N_   = 4096;
constexpr int T_   = 512;
constexpr int H_   = 64;
constexpr int G_   = 256;   // 4*H gates
constexpr int F_   = 16;
constexpr int HID_ = 256;
constexpr int NC_  = 10;

constexpr int STRIDE = 34;  // ull per k-row (32 rows + pad, keeps 16B align)

// --------------------------- scratch (device globals) ----------------------
__device__ float g_ft[(size_t)N_ * T_ * F_];          // features (n,t,f)
__device__ float g_h0[(size_t)T_ * (N_ / 32) * 2048]; // layer0 h: [t][blk][u][r]
__device__ float g_xs[(size_t)N_ * T_];               // h1 channel 0 -> (N,T)
__device__ float g_adj[(size_t)N_ * N_];
__device__ float g_mu[N_];
__device__ float g_sd[N_];
__device__ float g_d[N_];
__device__ float g_y[N_ * HID_];
__device__ float g_z[N_ * HID_];

typedef unsigned long long ull;

DEV_INLINE void fma2(ull& acc, ull a, ull b) {
    asm("fma.rn.f32x2 %0, %1, %2, %3;" : "=l"(acc) : "l"(a), "l"(b), "l"(acc));
}
DEV_INLINE ull pack2(float x) {
    ull r; asm("mov.b64 %0, {%1, %1};" : "=l"(r) : "f"(x)); return r;
}
DEV_INLINE ull packab(float lo, float hi) {
    ull r; asm("mov.b64 %0, {%1, %2};" : "=l"(r) : "f"(lo), "f"(hi)); return r;
}
DEV_INLINE float2 unpack2(ull v) {
    float2 f; asm("mov.b64 {%0, %1}, %2;" : "=f"(f.x), "=f"(f.y) : "l"(v)); return f;
}

DEV_INLINE float sigf(float x) { return 1.0f / (1.0f + __expf(-x)); }
DEV_INLINE float tanh_f(float x) {
    float a = fabsf(x);
    float e = __expf(-2.0f * a);
    float t = (1.0f - e) / (1.0f + e);
    return copysignf(t, x);
}

// --------------------------- feature transpose ------------------------------
__global__ __launch_bounds__(256)
void transpose_feat(const float* __restrict__ f, float* __restrict__ ft)
{
    __shared__ float s[16][516];
    int n = blockIdx.x;
    for (int idx = threadIdx.x; idx < F_ * T_; idx += 256) {
        int ff = idx >> 9, t = idx & 511;
        s[ff][t] = f[(size_t)n * (F_ * T_) + idx];
    }
    __syncthreads();
    for (int idx = threadIdx.x; idx < F_ * T_; idx += 256) {
        int t = idx >> 4, ff = idx & 15;
        ft[(size_t)n * (F_ * T_) + idx] = s[ff][t];
    }
}

// --------------------------- profiler alignment dummy -----------------------
__global__ void dummy_kernel(float* p) { if (threadIdx.x == 0) p[0] = 0.0f; }

// --------------------------- LSTM kernel -----------------------------------
// CTA = 32 batch rows, 512 threads. Thread (u = tid>>3, rg = tid&7) computes
// the 4 gates of unit u for rows 4rg..4rg+3. Weights gate-interleaved:
// Wt2[k][4u+j] = W[j*64+u][k], loaded per k as ulonglong2 (two f32x2 col
// pairs, no MOV broadcasts). Inputs stored DUPLICATED as f32x2 in smem:
// buf[k][r] = (x, x). Ping-pong buffers -> one barrier per step.
template <int KIN, int LAYER>
__global__ __launch_bounds__(512, 1)
void lstm_kernel(const float* __restrict__ src,     // L0: g_ft ; L1: g_h0
                 float* __restrict__ dst,           // L0: g_h0 ; L1: g_xs
                 const float* __restrict__ w_ih,
                 const float* __restrict__ w_hh,
                 const float* __restrict__ b_ih,
                 const float* __restrict__ b_hh)
{
    constexpr int KI = KIN - H_;   // 16 (L0) or 64 (L1)

    extern __shared__ float smem[];
    float* Wt2 = smem;                         // [KIN][256]
    ull*   buf = (ull*)(smem + KIN * G_);      // 2 x [KIN][STRIDE]

    const int tid = threadIdx.x;
    const int n0  = blockIdx.x * 32;
    const int u   = tid >> 3;                  // unit 0..63
    const int rg  = tid & 7;                   // rows 4rg..4rg+3

    // ---- gate-interleaved weights ----
    for (int idx = tid; idx < KIN * G_; idx += 512) {
        int k = idx >> 8, c = idx & 255;
        int uu = c >> 2, j = c & 3;
        Wt2[idx] = (k < KI) ? w_ih[(j * H_ + uu) * KI + k]
                            : w_hh[(j * H_ + uu) * H_ + (k - KI)];
    }
    // bias pairs: (b_i,b_f), (b_g,b_o) of unit u
    const ull bp0 = packab(b_ih[u] + b_hh[u],
                           b_ih[H_ + u] + b_hh[H_ + u]);
    const ull bp1 = packab(b_ih[2 * H_ + u] + b_hh[2 * H_ + u],
                           b_ih[3 * H_ + u] + b_hh[3 * H_ + u]);

    // zero both ping-pong buffers
    for (int idx = tid; idx < 2 * KIN * STRIDE; idx += 512) buf[idx] = 0ull;
    __syncthreads();

    // ---- stage x(0) into buffer 0 (duplicated) ----
    if constexpr (LAYER == 0) {
        int r = tid >> 4, f = tid & 15;
        buf[f * STRIDE + r] = pack2(src[((size_t)(n0 + r) * T_ + 0) * F_ + f]);
    } else {
        float4 v = *(const float4*)(src + (size_t)blockIdx.x * 2048 + tid * 4);
        int k = tid >> 3, r4 = (tid & 7) * 4;
        buf[k * STRIDE + r4 + 0] = pack2(v.x);
        buf[k * STRIDE + r4 + 1] = pack2(v.y);
        buf[k * STRIDE + r4 + 2] = pack2(v.z);
        buf[k * STRIDE + r4 + 3] = pack2(v.w);
    }
    __syncthreads();

    float c_reg[4] = {0.f, 0.f, 0.f, 0.f};
    float  pfx = 0.f;
    float4 pf4 = make_float4(0, 0, 0, 0);

    for (int t = 0; t < T_; t++) {
        const ull* cur = buf + (t & 1) * KIN * STRIDE;
        ull*       nxt = buf + ((t + 1) & 1) * KIN * STRIDE;

        // ---- prefetch x(t+1) ----
        if (t + 1 < T_) {
            if constexpr (LAYER == 0) {
                pfx = src[((size_t)(n0 + (tid >> 4)) * T_ + t + 1) * F_ + (tid & 15)];
            } else {
                pf4 = *(const float4*)(src + ((size_t)(t + 1) * (N_ / 32) + blockIdx.x) * 2048 + tid * 4);
            }
        }

        // ---- gate GEMM: 3 LDS.128 + 8 FFMA2 per k ----
        ull a00 = bp0, a01 = bp1, a10 = bp0, a11 = bp1;
        ull a20 = bp0, a21 = bp1, a30 = bp0, a31 = bp1;
        const float* wp = Wt2 + 4 * u;
        const ull*   ip = cur + rg * 4;
#pragma unroll 4
        for (int k = 0; k < KIN; k++) {
            ulonglong2 wv  = *(const ulonglong2*)(wp + (size_t)k * G_);
            ulonglong2 x01 = *(const ulonglong2*)(ip + k * STRIDE);
            ulonglong2 x23 = *(const ulonglong2*)(ip + k * STRIDE + 2);
            fma2(a00, x01.x, wv.x); fma2(a01, x01.x, wv.y);
            fma2(a10, x01.y, wv.x); fma2(a11, x01.y, wv.y);
            fma2(a20, x23.x, wv.x); fma2(a21, x23.x, wv.y);
            fma2(a30, x23.y, wv.x); fma2(a31, x23.y, wv.y);
        }

        // ---- activations + state update (4 rows of unit u) ----
        float h[4];
        {
            float2 gif, ggo; float c;
            gif = unpack2(a00); ggo = unpack2(a01);
            c = sigf(gif.y) * c_reg[0] + sigf(gif.x) * tanh_f(ggo.x);
            c_reg[0] = c; h[0] = sigf(ggo.y) * tanh_f(c);
            gif = unpack2(a10); ggo = unpack2(a11);
            c = sigf(gif.y) * c_reg[1] + sigf(gif.x) * tanh_f(ggo.x);
            c_reg[1] = c; h[1] = sigf(ggo.y) * tanh_f(c);
            gif = unpack2(a20); ggo = unpack2(a21);
            c = sigf(gif.y) * c_reg[2] + sigf(gif.x) * tanh_f(ggo.x);
            c_reg[2] = c; h[2] = sigf(ggo.y) * tanh_f(c);
            gif = unpack2(a30); ggo = unpack2(a31);
            c = sigf(gif.y) * c_reg[3] + sigf(gif.x) * tanh_f(ggo.x);
            c_reg[3] = c; h[3] = sigf(ggo.y) * tanh_f(c);
        }

        // ---- stage h(t) into nxt (duplicated) ----
        {
            ull* hp = nxt + (KI + u) * STRIDE + rg * 4;
            hp[0] = pack2(h[0]); hp[1] = pack2(h[1]);
            hp[2] = pack2(h[2]); hp[3] = pack2(h[3]);
        }

        // ---- commit prefetched x(t+1) into nxt ----
        if (t + 1 < T_) {
            if constexpr (LAYER == 0) {
                nxt[(tid & 15) * STRIDE + (tid >> 4)] = pack2(pfx);
            } else {
                int k = tid >> 3, r4 = (tid & 7) * 4;
                nxt[k * STRIDE + r4 + 0] = pack2(pf4.x);
                nxt[k * STRIDE + r4 + 1] = pack2(pf4.y);
                nxt[k * STRIDE + r4 + 2] = pack2(pf4.z);
                nxt[k * STRIDE + r4 + 3] = pack2(pf4.w);
            }
        }

        // ---- global outputs ----
        if constexpr (LAYER == 0) {
            // blocked layout: offset u*32 + rg*4 == tid*4 (fully coalesced)
            *(float4*)(dst + ((size_t)t * (N_ / 32) + blockIdx.x) * 2048 + tid * 4)
                = make_float4(h[0], h[1], h[2], h[3]);
        } else {
            if (u == 0) {
#pragma unroll
                for (int p = 0; p < 4; p++)
                    dst[(size_t)(n0 + rg * 4 + p) * T_ + t] = h[p];
            }
        }

        __syncthreads();
    }
}

// --------------------------- row stats (mu, std) ----------------------------
__global__ __launch_bounds__(256)
void stats_kernel(const float* __restrict__ xs, float* __restrict__ mu,
                  float* __restrict__ sd)
{
    __shared__ float sh[8], sh2[8];
    int n = blockIdx.x, tid = threadIdx.x;
    float s = 0.f, s2 = 0.f;
    for (int t = tid; t < T_; t += 256) {
        float v = xs[(size_t)n * T_ + t];
        s += v; s2 += v * v;
    }
#pragma unroll
    for (int o = 16; o; o >>= 1) {
        s  += __shfl_xor_sync(0xffffffffu, s, o);
        s2 += __shfl_xor_sync(0xffffffffu, s2, o);
    }
    if ((tid & 31) == 0) { sh[tid >> 5] = s; sh2[tid >> 5] = s2; }
    __syncthreads();
    if (tid == 0) {
        float ts = 0.f, ts2 = 0.f;
        for (int w = 0; w < 8; w++) { ts += sh[w]; ts2 += sh2[w]; }
        float m = ts * (1.0f / T_);
        float var = ts2 * (1.0f / T_) - m * m;
        mu[n] = m;
        sd[n] = sqrtf(fmaxf(var, 0.0f));
    }
}

// --------------------------- corr GEMM (X X^T -> adj), f32x2 ---------------
__global__ __launch_bounds__(256)
void corr_kernel(const float* __restrict__ X, float* __restrict__ adj,
                 const float* __restrict__ mu, const float* __restrict__ sd)
{
    if (blockIdx.x < blockIdx.y) return;
    __shared__ float As[16][68];
    __shared__ float Bs[16][68];
    const int tid = threadIdx.x;
    const int tx = tid & 15, ty = tid >> 4;
    const int row0 = blockIdx.y * 64, col0 = blockIdx.x * 64;
    const int ar = tid >> 2, ac = (tid & 3) << 2;
    ull acc2[2][4];
#pragma unroll
    for (int i = 0; i < 2; i++)
#pragma unroll
        for (int j = 0; j < 4; j++) acc2[i][j] = 0ull;

    for (int k0 = 0; k0 < T_; k0 += 16) {
        float4 a4 = *(const float4*)&X[(size_t)(row0 + ar) * T_ + k0 + ac];
        As[ac + 0][ar] = a4.x; As[ac + 1][ar] = a4.y;
        As[ac + 2][ar] = a4.z; As[ac + 3][ar] = a4.w;
        float4 b4 = *(const float4*)&X[(size_t)(col0 + ar) * T_ + k0 + ac];
        Bs[ac + 0][ar] = b4.x; Bs[ac + 1][ar] = b4.y;
        Bs[ac + 2][ar] = b4.z; Bs[ac + 3][ar] = b4.w;
        __syncthreads();
#pragma unroll
        for (int k = 0; k < 16; k++) {
            float4 av = *(const float4*)&As[k][ty << 2];
            float4 bv = *(const float4*)&Bs[k][tx << 2];
            ull a01 = packab(av.x, av.y), a23 = packab(av.z, av.w);
            ull b0 = pack2(bv.x), b1 = pack2(bv.y), b2 = pack2(bv.z), b3 = pack2(bv.w);
            fma2(acc2[0][0], a01, b0); fma2(acc2[1][0], a23, b0);
            fma2(acc2[0][1], a01, b1); fma2(acc2[1][1], a23, b1);
            fma2(acc2[0][2], a01, b2); fma2(acc2[1][2], a23, b2);
            fma2(acc2[0][3], a01, b3); fma2(acc2[1][3], a23, b3);
        }
        __syncthreads();
    }
    float acc[4][4];
#pragma unroll
    for (int j = 0; j < 4; j++) {
        float2 r01 = unpack2(acc2[0][j]);
        float2 r23 = unpack2(acc2[1][j]);
        acc[0][j] = r01.x; acc[1][j] = r01.y; acc[2][j] = r23.x; acc[3][j] = r23.y;
    }
#pragma unroll
    for (int i = 0; i < 4; i++) {
        int gi = row0 + (ty << 2) + i;
        float mi = mu[gi], si = sd[gi];
#pragma unroll
        for (int j = 0; j < 4; j++) {
            int gj = col0 + (tx << 2) + j;
            float cov = acc[i][j] * (1.0f / T_) - mi * mu[gj];
            float den = si * sd[gj];
            float corr = (den == 0.0f) ? 0.0f : cov / den;
            float a = corr + ((gi == gj) ? 1.0f : 0.0f);
            adj[(size_t)gi * N_ + gj] = a;
            adj[(size_t)gj * N_ + gi] = a;
        }
    }
}

// --------------------------- rowsum -> d = rs^-0.5 --------------------------
__global__ __launch_bounds__(256)
void rowsum_kernel(const float* __restrict__ adj, float* __restrict__ dvec)
{
    __shared__ float sh[8];
    int i = blockIdx.x, tid = threadIdx.x;
    float s = 0.f;
    for (int j = tid; j < N_; j += 256) s += adj[(size_t)i * N_ + j];
#pragma unroll
    for (int o = 16; o; o >>= 1) s += __shfl_xor_sync(0xffffffffu, s, o);
    if ((tid & 31) == 0) sh[tid >> 5] = s;
    __syncthreads();
    if (tid == 0) {
        float ts = 0.f;
        for (int w = 0; w < 8; w++) ts += sh[w];
        dvec[i] = (ts > 0.0f) ? (1.0f / sqrtf(ts)) : 0.0f;
    }
}

// --------------------------- tiled GEMM (NN), f32x2, epilogues --------------
template <int MODE>
__global__ __launch_bounds__(256)
void gemm_nn(const float* __restrict__ A, const float* __restrict__ B,
             float* __restrict__ C, int M, int N, int K,
             const float* __restrict__ dvec, const float* __restrict__ bias)
{
    __shared__ float As[16][68];
    __shared__ float Bs[16][64];
    const int tid = threadIdx.x;
    const int tx = tid & 15, ty = tid >> 4;
    const int row0 = blockIdx.y * 64, col0 = blockIdx.x * 64;
    const int ar = tid >> 2, ac = (tid & 3) << 2;
    const int br = tid >> 4, bc = (tid & 15) << 2;
    ull acc2[2][4];
#pragma unroll
    for (int i = 0; i < 2; i++)
#pragma unroll
        for (int j = 0; j < 4; j++) acc2[i][j] = 0ull;

    for (int k0 = 0; k0 < K; k0 += 16) {
        float4 a4 = *(const float4*)&A[(size_t)(row0 + ar) * K + k0 + ac];
        As[ac + 0][ar] = a4.x; As[ac + 1][ar] = a4.y;
        As[ac + 2][ar] = a4.z; As[ac + 3][ar] = a4.w;
        *(float4*)&Bs[br][bc] = *(const float4*)&B[(size_t)(k0 + br) * N + col0 + bc];
        __syncthreads();
#pragma unroll
        for (int k = 0; k < 16; k++) {
            float4 av = *(const float4*)&As[k][ty << 2];
            float4 bv = *(const float4*)&Bs[k][tx << 2];
            ull a01 = packab(av.x, av.y), a23 = packab(av.z, av.w);
            ull b0 = pack2(bv.x), b1 = pack2(bv.y), b2 = pack2(bv.z), b3 = pack2(bv.w);
            fma2(acc2[0][0], a01, b0); fma2(acc2[1][0], a23, b0);
            fma2(acc2[0][1], a01, b1); fma2(acc2[1][1], a23, b1);
            fma2(acc2[0][2], a01, b2); fma2(acc2[1][2], a23, b2);
            fma2(acc2[0][3], a01, b3); fma2(acc2[1][3], a23, b3);
        }
        __syncthreads();
    }
    float acc[4][4];
#pragma unroll
    for (int j = 0; j < 4; j++) {
        float2 r01 = unpack2(acc2[0][j]);
        float2 r23 = unpack2(acc2[1][j]);
        acc[0][j] = r01.x; acc[1][j] = r01.y; acc[2][j] = r23.x; acc[3][j] = r23.y;
    }
#pragma unroll
    for (int i = 0; i < 4; i++) {
        int gi = row0 + (ty << 2) + i;
        float dv = dvec[gi];
#pragma unroll
        for (int j = 0; j < 4; j++) {
            int gj = col0 + (tx << 2) + j;
            float v = acc[i][j];
            if (MODE == 1) v = dv * v;
            if (MODE == 2) { v = dv * v + bias[gj]; v = fmaxf(v, 0.0f); }
            C[(size_t)gi * N + gj] = v;
        }
    }
}

// --------------------------- classifier -------------------------------------
__global__ void clf_kernel(const float* __restrict__ z, const float* __restrict__ w,
                           const float* __restrict__ b, float* __restrict__ out)
{
    int idx = blockIdx.x * blockDim.x + threadIdx.x;
    if (idx >= N_ * NC_) return;
    int n = idx / NC_, c = idx - n * NC_;
    float s = b[c];
    const float* zr = z + (size_t)n * HID_;
#pragma unroll 8
    for (int h = 0; h < HID_; h++) s += zr[h] * w[h * NC_ + c];
    out[idx] = s;
}

// --------------------------- launch ------------------------------------------
extern "C" void kernel_launch(void* const* d_in, const int* in_sizes, int n_in,
                              void* d_out, int out_size)
{
    const float* features = (const float*)d_in[0];
    const float* w_ih0 = (const float*)d_in[1];
    const float* w_hh0 = (const float*)d_in[2];
    const float* b_ih0 = (const float*)d_in[3];
    const float* b_hh0 = (const float*)d_in[4];
    const float* w_ih1 = (const float*)d_in[5];
    const float* w_hh1 = (const float*)d_in[6];
    const float* b_ih1 = (const float*)d_in[7];
    const float* b_hh1 = (const float*)d_in[8];
    const float* gc1_w = (const float*)d_in[9];
    const float* gc1_b = (const float*)d_in[10];
    const float* gc2_w = (const float*)d_in[11];
    const float* gc2_b = (const float*)d_in[12];
    const float* clf_w = (const float*)d_in[13];
    const float* clf_b = (const float*)d_in[14];
    float* out = (float*)d_out;

    float *p_ft, *p_h0, *p_xs, *p_adj, *p_mu, *p_sd, *p_d, *p_y, *p_z;
    cudaGetSymbolAddress((void**)&p_ft,  g_ft);
    cudaGetSymbolAddress((void**)&p_h0,  g_h0);
    cudaGetSymbolAddress((void**)&p_xs,  g_xs);
    cudaGetSymbolAddress((void**)&p_adj, g_adj);
    cudaGetSymbolAddress((void**)&p_mu,  g_mu);
    cudaGetSymbolAddress((void**)&p_sd,  g_sd);
    cudaGetSymbolAddress((void**)&p_d,   g_d);
    cudaGetSymbolAddress((void**)&p_y,   g_y);
    cudaGetSymbolAddress((void**)&p_z,   g_z);

    const int smem0 = 80  * G_ * 4 + 2 * 80  * STRIDE * 8;  // 125440 B
    const int smem1 = 128 * G_ * 4 + 2 * 128 * STRIDE * 8;  // 200704 B
    cudaFuncSetAttribute((const void*)lstm_kernel<80, 0>,
                         cudaFuncAttributeMaxDynamicSharedMemorySize, smem0);
    cudaFuncSetAttribute((const void*)lstm_kernel<128, 1>,
                         cudaFuncAttributeMaxDynamicSharedMemorySize, smem1);

    // features (N,F,T) -> (N,T,F)
    transpose_feat<<<N_, 256>>>(features, p_ft);

    // LSTM layer 0: g_ft -> g_h0 (blocked [t][blk][u][r])
    lstm_kernel<80, 0><<<N_ / 32, 512, smem0>>>(p_ft, p_h0, w_ih0, w_hh0, b_ih0, b_hh0);

    // dummy launch so ncu's fixed window (4th launch) profiles lstm layer 1
    dummy_kernel<<<1, 32>>>(p_mu);

    // LSTM layer 1: g_h0 -> g_xs (channel 0)
    lstm_kernel<128, 1><<<N_ / 32, 512, smem1>>>(p_h0, p_xs, w_ih1, w_hh1, b_ih1, b_hh1);

    // adjacency
    stats_kernel<<<N_, 256>>>(p_xs, p_mu, p_sd);
    corr_kernel<<<dim3(N_ / 64, N_ / 64), 256>>>(p_xs, p_adj, p_mu, p_sd);
    rowsum_kernel<<<N_, 256>>>(p_adj, p_d);

    // GCN
    gemm_nn<1><<<dim3(HID_ / 64, N_ / 64), 256>>>(p_xs,  gc1_w, p_y, N_, HID_, T_,   p_d, nullptr);
    gemm_nn<2><<<dim3(HID_ / 64, N_ / 64), 256>>>(p_adj, p_y,   p_z, N_, HID_, N_,   p_d, gc1_b);
    gemm_nn<1><<<dim3(HID_ / 64, N_ / 64), 256>>>(p_z,   gc2_w, p_y, N_, HID_, HID_, p_d, nullptr);
    gemm_nn<2><<<dim3(HID_ / 64, N_ / 64), 256>>>(p_adj, p_y,   p_z, N_, HID_, N_,   p_d, gc2_b);

    // classifier
    clf_kernel<<<(N_ * NC_ + 255) / 256, 256>>>(p_z, clf_w, clf_b, out);
}

// round 6
// speedup vs baseline: 2.2985x; 2.2985x over previous
#include <cuda_runtime.h>
#include <math.h>

// ---------------------------------------------------------------------------
// GCN_45921790329163
// R5: revert to proven 7710us LSTM (fused phases, ping-pong, f32x2 row-pairs)
//     + blocked g_h0 layout (coalesced layer0 stores / layer1 loads).
// ---------------------------------------------------------------------------

#define DEV_INLINE __device__ __forceinline__

constexpr int N_   = 4096;
constexpr int T_   = 512;
constexpr int H_   = 64;
constexpr int G_   = 256;   // 4*H gates
constexpr int F_   = 16;
constexpr int HID_ = 256;
constexpr int NC_  = 10;

constexpr int INROW_  = 18;   // ull per k-row (16 data + 2 pad)
constexpr int INROWF_ = 36;   // floats per k-row

// --------------------------- scratch (device globals) ----------------------
__device__ float g_ft[(size_t)N_ * T_ * F_];          // features (n,t,f)
__device__ float g_h0[(size_t)T_ * (N_ / 32) * 2048]; // layer0 h: [t][blk][u][r]
__device__ float g_xs[(size_t)N_ * T_];               // h1 channel 0 -> (N,T)
__device__ float g_adj[(size_t)N_ * N_];
__device__ float g_mu[N_];
__device__ float g_sd[N_];
__device__ float g_d[N_];
__device__ float g_y[N_ * HID_];
__device__ float g_z[N_ * HID_];

typedef unsigned long long ull;

DEV_INLINE void fma2(ull& acc, ull a, ull b) {
    asm("fma.rn.f32x2 %0, %1, %2, %3;" : "=l"(acc) : "l"(a), "l"(b), "l"(acc));
}
DEV_INLINE ull pack2(float x) {
    ull r; asm("mov.b64 %0, {%1, %1};" : "=l"(r) : "f"(x)); return r;
}
DEV_INLINE ull packab(float lo, float hi) {
    ull r; asm("mov.b64 %0, {%1, %2};" : "=l"(r) : "f"(lo), "f"(hi)); return r;
}
DEV_INLINE float2 unpack2(ull v) {
    float2 f; asm("mov.b64 {%0, %1}, %2;" : "=f"(f.x), "=f"(f.y) : "l"(v)); return f;
}

DEV_INLINE float sigf(float x) { return 1.0f / (1.0f + __expf(-x)); }
DEV_INLINE float tanh_f(float x) {
    float a = fabsf(x);
    float e = __expf(-2.0f * a);
    float t = (1.0f - e) / (1.0f + e);
    return copysignf(t, x);
}

// --------------------------- feature transpose ------------------------------
__global__ __launch_bounds__(256)
void transpose_feat(const float* __restrict__ f, float* __restrict__ ft)
{
    __shared__ float s[16][516];
    int n = blockIdx.x;
    for (int idx = threadIdx.x; idx < F_ * T_; idx += 256) {
        int ff = idx >> 9, t = idx & 511;
        s[ff][t] = f[(size_t)n * (F_ * T_) + idx];
    }
    __syncthreads();
    for (int idx = threadIdx.x; idx < F_ * T_; idx += 256) {
        int t = idx >> 4, ff = idx & 15;
        ft[(size_t)n * (F_ * T_) + idx] = s[ff][t];
    }
}

// --------------------------- profiler alignment dummy -----------------------
__global__ void dummy_kernel(float* p) { if (threadIdx.x == 0) p[0] = 0.0f; }

// --------------------------- LSTM kernel -----------------------------------
// CTA = 32 batch rows, 512 threads. Thread (u = tid>>3, rg = tid&7) computes
// gates i,f,g,o of unit u for rows 4rg..4rg+3 (f32x2 over row pairs).
// Weights gate-interleaved: Wt2[k][4u+j] = W[j*64+u][k] (one float4/k).
// Inputs in ping-pong smem as natural floats [k][32+pad]; one barrier/step.
template <int KIN, int LAYER>
__global__ __launch_bounds__(512, 1)
void lstm_kernel(const float* __restrict__ src,     // L0: g_ft ; L1: g_h0 blocked
                 float* __restrict__ dst,           // L0: g_h0 blocked ; L1: g_xs
                 const float* __restrict__ w_ih,
                 const float* __restrict__ w_hh,
                 const float* __restrict__ b_ih,
                 const float* __restrict__ b_hh)
{
    constexpr int KI = KIN - H_;     // 16 (L0) or 64 (L1); h lives at rows KI..

    extern __shared__ float smem[];
    float* Wt2  = smem;                        // [KIN][256] gate-interleaved
    float* in2f = Wt2 + KIN * G_;              // 2 x [KIN][36] ping-pong

    const int tid = threadIdx.x;
    const int n0  = blockIdx.x * 32;
    const int u   = tid >> 3;        // unit 0..63
    const int rg  = tid & 7;         // row group: rows 4rg..4rg+3

    // ---- fill gate-interleaved weights Wt2[k][4u+j] ----
    for (int idx = tid; idx < KIN * G_; idx += 512) {
        int k = idx >> 8, c = idx & 255;
        int uu = c >> 2, j = c & 3;
        int row = j * H_ + uu;                 // torch gate-major row
        Wt2[idx] = (k < KI) ? w_ih[row * KI + k] : w_hh[row * H_ + (k - KI)];
    }
    // zero both ping-pong buffers
    for (int idx = tid; idx < 2 * KIN * INROWF_; idx += 512) in2f[idx] = 0.0f;

    // bias in registers (4 gates of unit u)
    float bj[4];
#pragma unroll
    for (int j = 0; j < 4; j++) bj[j] = b_ih[j * H_ + u] + b_hh[j * H_ + u];

    __syncthreads();

    // ---- stage x(0) into buffer 0 ----
    if constexpr (LAYER == 0) {
        int r = tid >> 4, f = tid & 15;
        in2f[f * INROWF_ + r] = src[((size_t)(n0 + r) * T_ + 0) * F_ + f];
    } else {
        // blocked layout: element tid*4 = unit (tid>>3), rows (tid&7)*4..+3
        float4 hv = *(const float4*)(src + (size_t)blockIdx.x * 2048 + tid * 4);
        *(float4*)&in2f[(tid >> 3) * INROWF_ + (tid & 7) * 4] = hv;
    }
    __syncthreads();

    float c_reg[4];
#pragma unroll
    for (int p = 0; p < 4; p++) c_reg[p] = 0.0f;

    float  xv = 0.f;
    float4 hv = make_float4(0, 0, 0, 0);

    for (int t = 0; t < T_; t++) {
        const float* cur = in2f + (t & 1) * KIN * INROWF_;
        float*       nxt = in2f + ((t + 1) & 1) * KIN * INROWF_;
        const ull*   in2c = (const ull*)cur;

        // ---- prefetch x(t+1) (committed to nxt after compute) ----
        if (t + 1 < T_) {
            if constexpr (LAYER == 0) {
                xv = src[((size_t)(n0 + (tid >> 4)) * T_ + t + 1) * F_ + (tid & 15)];
            } else {
                hv = *(const float4*)(src + ((size_t)(t + 1) * (N_ / 32) + blockIdx.x) * 2048 + tid * 4);
            }
        }

        // ---- gates: acc[j][pair] = b_j + sum_k Wt2[k][4u+j] * in[k][rows] ----
        ull acc0[2], acc1[2], acc2[2], acc3[2];
        acc0[0] = acc0[1] = pack2(bj[0]);
        acc1[0] = acc1[1] = pack2(bj[1]);
        acc2[0] = acc2[1] = pack2(bj[2]);
        acc3[0] = acc3[1] = pack2(bj[3]);

#pragma unroll 4
        for (int k = 0; k < KIN; k++) {
            float4 w = *(const float4*)&Wt2[k * G_ + 4 * u];
            ull w0 = pack2(w.x), w1 = pack2(w.y), w2 = pack2(w.z), w3 = pack2(w.w);
            ulonglong2 v = *(const ulonglong2*)(in2c + k * INROW_ + 2 * rg);
            fma2(acc0[0], v.x, w0); fma2(acc0[1], v.y, w0);
            fma2(acc1[0], v.x, w1); fma2(acc1[1], v.y, w1);
            fma2(acc2[0], v.x, w2); fma2(acc2[1], v.y, w2);
            fma2(acc3[0], v.x, w3); fma2(acc3[1], v.y, w3);
        }

        // ---- activations + state update for 4 rows of unit u ----
        float gi[4], gf[4], gg[4], go[4];
        {
            float2 a = unpack2(acc0[0]), b = unpack2(acc0[1]);
            gi[0] = a.x; gi[1] = a.y; gi[2] = b.x; gi[3] = b.y;
            a = unpack2(acc1[0]); b = unpack2(acc1[1]);
            gf[0] = a.x; gf[1] = a.y; gf[2] = b.x; gf[3] = b.y;
            a = unpack2(acc2[0]); b = unpack2(acc2[1]);
            gg[0] = a.x; gg[1] = a.y; gg[2] = b.x; gg[3] = b.y;
            a = unpack2(acc3[0]); b = unpack2(acc3[1]);
            go[0] = a.x; go[1] = a.y; go[2] = b.x; go[3] = b.y;
        }
        float4 hout;
        float* hp = (float*)&hout;
#pragma unroll
        for (int p = 0; p < 4; p++) {
            float c = sigf(gf[p]) * c_reg[p] + sigf(gi[p]) * tanh_f(gg[p]);
            c_reg[p] = c;
            hp[p] = sigf(go[p]) * tanh_f(c);
        }

        // ---- stage h(t) into nxt buffer (STS.128, aligned) ----
        *(float4*)&nxt[(KI + u) * INROWF_ + 4 * rg] = hout;

        // ---- commit prefetched x(t+1) into nxt ----
        if (t + 1 < T_) {
            if constexpr (LAYER == 0) {
                nxt[(tid & 15) * INROWF_ + (tid >> 4)] = xv;
            } else {
                *(float4*)&nxt[(tid >> 3) * INROWF_ + (tid & 7) * 4] = hv;
            }
        }

        // ---- global outputs ----
        if constexpr (LAYER == 0) {
            // blocked layout: offset u*32 + 4rg == tid*4 -> one coalesced STG.128
            *(float4*)(dst + ((size_t)t * (N_ / 32) + blockIdx.x) * 2048 + tid * 4) = hout;
        } else {
            if (u == 0) {
#pragma unroll
                for (int p = 0; p < 4; p++)
                    dst[(size_t)(n0 + rg * 4 + p) * T_ + t] = hp[p];
            }
        }

        __syncthreads();   // nxt fully written before step t+1 reads it
    }
}

// --------------------------- row stats (mu, std) ----------------------------
__global__ __launch_bounds__(256)
void stats_kernel(const float* __restrict__ xs, float* __restrict__ mu,
                  float* __restrict__ sd)
{
    __shared__ float sh[8], sh2[8];
    int n = blockIdx.x, tid = threadIdx.x;
    float s = 0.f, s2 = 0.f;
    for (int t = tid; t < T_; t += 256) {
        float v = xs[(size_t)n * T_ + t];
        s += v; s2 += v * v;
    }
#pragma unroll
    for (int o = 16; o; o >>= 1) {
        s  += __shfl_xor_sync(0xffffffffu, s, o);
        s2 += __shfl_xor_sync(0xffffffffu, s2, o);
    }
    if ((tid & 31) == 0) { sh[tid >> 5] = s; sh2[tid >> 5] = s2; }
    __syncthreads();
    if (tid == 0) {
        float ts = 0.f, ts2 = 0.f;
        for (int w = 0; w < 8; w++) { ts += sh[w]; ts2 += sh2[w]; }
        float m = ts * (1.0f / T_);
        float var = ts2 * (1.0f / T_) - m * m;
        mu[n] = m;
        sd[n] = sqrtf(fmaxf(var, 0.0f));
    }
}

// --------------------------- corr GEMM (X X^T -> adj), f32x2 ---------------
__global__ __launch_bounds__(256)
void corr_kernel(const float* __restrict__ X, float* __restrict__ adj,
                 const float* __restrict__ mu, const float* __restrict__ sd)
{
    if (blockIdx.x < blockIdx.y) return;
    __shared__ float As[16][68];
    __shared__ float Bs[16][68];
    const int tid = threadIdx.x;
    const int tx = tid & 15, ty = tid >> 4;
    const int row0 = blockIdx.y * 64, col0 = blockIdx.x * 64;
    const int ar = tid >> 2, ac = (tid & 3) << 2;
    ull acc2[2][4];
#pragma unroll
    for (int i = 0; i < 2; i++)
#pragma unroll
        for (int j = 0; j < 4; j++) acc2[i][j] = 0ull;

    for (int k0 = 0; k0 < T_; k0 += 16) {
        float4 a4 = *(const float4*)&X[(size_t)(row0 + ar) * T_ + k0 + ac];
        As[ac + 0][ar] = a4.x; As[ac + 1][ar] = a4.y;
        As[ac + 2][ar] = a4.z; As[ac + 3][ar] = a4.w;
        float4 b4 = *(const float4*)&X[(size_t)(col0 + ar) * T_ + k0 + ac];
        Bs[ac + 0][ar] = b4.x; Bs[ac + 1][ar] = b4.y;
        Bs[ac + 2][ar] = b4.z; Bs[ac + 3][ar] = b4.w;
        __syncthreads();
#pragma unroll
        for (int k = 0; k < 16; k++) {
            float4 av = *(const float4*)&As[k][ty << 2];
            float4 bv = *(const float4*)&Bs[k][tx << 2];
            ull a01 = packab(av.x, av.y), a23 = packab(av.z, av.w);
            ull b0 = pack2(bv.x), b1 = pack2(bv.y), b2 = pack2(bv.z), b3 = pack2(bv.w);
            fma2(acc2[0][0], a01, b0); fma2(acc2[1][0], a23, b0);
            fma2(acc2[0][1], a01, b1); fma2(acc2[1][1], a23, b1);
            fma2(acc2[0][2], a01, b2); fma2(acc2[1][2], a23, b2);
            fma2(acc2[0][3], a01, b3); fma2(acc2[1][3], a23, b3);
        }
        __syncthreads();
    }
    float acc[4][4];
#pragma unroll
    for (int j = 0; j < 4; j++) {
        float2 r01 = unpack2(acc2[0][j]);
        float2 r23 = unpack2(acc2[1][j]);
        acc[0][j] = r01.x; acc[1][j] = r01.y; acc[2][j] = r23.x; acc[3][j] = r23.y;
    }
#pragma unroll
    for (int i = 0; i < 4; i++) {
        int gi = row0 + (ty << 2) + i;
        float mi = mu[gi], si = sd[gi];
#pragma unroll
        for (int j = 0; j < 4; j++) {
            int gj = col0 + (tx << 2) + j;
            float cov = acc[i][j] * (1.0f / T_) - mi * mu[gj];
            float den = si * sd[gj];
            float corr = (den == 0.0f) ? 0.0f : cov / den;
            float a = corr + ((gi == gj) ? 1.0f : 0.0f);
            adj[(size_t)gi * N_ + gj] = a;
            adj[(size_t)gj * N_ + gi] = a;
        }
    }
}

// --------------------------- rowsum -> d = rs^-0.5 --------------------------
__global__ __launch_bounds__(256)
void rowsum_kernel(const float* __restrict__ adj, float* __restrict__ dvec)
{
    __shared__ float sh[8];
    int i = blockIdx.x, tid = threadIdx.x;
    float s = 0.f;
    for (int j = tid; j < N_; j += 256) s += adj[(size_t)i * N_ + j];
#pragma unroll
    for (int o = 16; o; o >>= 1) s += __shfl_xor_sync(0xffffffffu, s, o);
    if ((tid & 31) == 0) sh[tid >> 5] = s;
    __syncthreads();
    if (tid == 0) {
        float ts = 0.f;
        for (int w = 0; w < 8; w++) ts += sh[w];
        dvec[i] = (ts > 0.0f) ? (1.0f / sqrtf(ts)) : 0.0f;
    }
}

// --------------------------- tiled GEMM (NN), f32x2, epilogues --------------
template <int MODE>
__global__ __launch_bounds__(256)
void gemm_nn(const float* __restrict__ A, const float* __restrict__ B,
             float* __restrict__ C, int M, int N, int K,
             const float* __restrict__ dvec, const float* __restrict__ bias)
{
    __shared__ float As[16][68];
    __shared__ float Bs[16][64];
    const int tid = threadIdx.x;
    const int tx = tid & 15, ty = tid >> 4;
    const int row0 = blockIdx.y * 64, col0 = blockIdx.x * 64;
    const int ar = tid >> 2, ac = (tid & 3) << 2;
    const int br = tid >> 4, bc = (tid & 15) << 2;
    ull acc2[2][4];
#pragma unroll
    for (int i = 0; i < 2; i++)
#pragma unroll
        for (int j = 0; j < 4; j++) acc2[i][j] = 0ull;

    for (int k0 = 0; k0 < K; k0 += 16) {
        float4 a4 = *(const float4*)&A[(size_t)(row0 + ar) * K + k0 + ac];
        As[ac + 0][ar] = a4.x; As[ac + 1][ar] = a4.y;
        As[ac + 2][ar] = a4.z; As[ac + 3][ar] = a4.w;
        *(float4*)&Bs[br][bc] = *(const float4*)&B[(size_t)(k0 + br) * N + col0 + bc];
        __syncthreads();
#pragma unroll
        for (int k = 0; k < 16; k++) {
            float4 av = *(const float4*)&As[k][ty << 2];
            float4 bv = *(const float4*)&Bs[k][tx << 2];
            ull a01 = packab(av.x, av.y), a23 = packab(av.z, av.w);
            ull b0 = pack2(bv.x), b1 = pack2(bv.y), b2 = pack2(bv.z), b3 = pack2(bv.w);
            fma2(acc2[0][0], a01, b0); fma2(acc2[1][0], a23, b0);
            fma2(acc2[0][1], a01, b1); fma2(acc2[1][1], a23, b1);
            fma2(acc2[0][2], a01, b2); fma2(acc2[1][2], a23, b2);
            fma2(acc2[0][3], a01, b3); fma2(acc2[1][3], a23, b3);
        }
        __syncthreads();
    }
    float acc[4][4];
#pragma unroll
    for (int j = 0; j < 4; j++) {
        float2 r01 = unpack2(acc2[0][j]);
        float2 r23 = unpack2(acc2[1][j]);
        acc[0][j] = r01.x; acc[1][j] = r01.y; acc[2][j] = r23.x; acc[3][j] = r23.y;
    }
#pragma unroll
    for (int i = 0; i < 4; i++) {
        int gi = row0 + (ty << 2) + i;
        float dv = dvec[gi];
#pragma unroll
        for (int j = 0; j < 4; j++) {
            int gj = col0 + (tx << 2) + j;
            float v = acc[i][j];
            if (MODE == 1) v = dv * v;
            if (MODE == 2) { v = dv * v + bias[gj]; v = fmaxf(v, 0.0f); }
            C[(size_t)gi * N + gj] = v;
        }
    }
}

// --------------------------- classifier -------------------------------------
__global__ void clf_kernel(const float* __restrict__ z, const float* __restrict__ w,
                           const float* __restrict__ b, float* __restrict__ out)
{
    int idx = blockIdx.x * blockDim.x + threadIdx.x;
    if (idx >= N_ * NC_) return;
    int n = idx / NC_, c = idx - n * NC_;
    float s = b[c];
    const float* zr = z + (size_t)n * HID_;
#pragma unroll 8
    for (int h = 0; h < HID_; h++) s += zr[h] * w[h * NC_ + c];
    out[idx] = s;
}

// --------------------------- launch ------------------------------------------
extern "C" void kernel_launch(void* const* d_in, const int* in_sizes, int n_in,
                              void* d_out, int out_size)
{
    const float* features = (const float*)d_in[0];
    const float* w_ih0 = (const float*)d_in[1];
    const float* w_hh0 = (const float*)d_in[2];
    const float* b_ih0 = (const float*)d_in[3];
    const float* b_hh0 = (const float*)d_in[4];
    const float* w_ih1 = (const float*)d_in[5];
    const float* w_hh1 = (const float*)d_in[6];
    const float* b_ih1 = (const float*)d_in[7];
    const float* b_hh1 = (const float*)d_in[8];
    const float* gc1_w = (const float*)d_in[9];
    const float* gc1_b = (const float*)d_in[10];
    const float* gc2_w = (const float*)d_in[11];
    const float* gc2_b = (const float*)d_in[12];
    const float* clf_w = (const float*)d_in[13];
    const float* clf_b = (const float*)d_in[14];
    float* out = (float*)d_out;

    float *p_ft, *p_h0, *p_xs, *p_adj, *p_mu, *p_sd, *p_d, *p_y, *p_z;
    cudaGetSymbolAddress((void**)&p_ft,  g_ft);
    cudaGetSymbolAddress((void**)&p_h0,  g_h0);
    cudaGetSymbolAddress((void**)&p_xs,  g_xs);
    cudaGetSymbolAddress((void**)&p_adj, g_adj);
    cudaGetSymbolAddress((void**)&p_mu,  g_mu);
    cudaGetSymbolAddress((void**)&p_sd,  g_sd);
    cudaGetSymbolAddress((void**)&p_d,   g_d);
    cudaGetSymbolAddress((void**)&p_y,   g_y);
    cudaGetSymbolAddress((void**)&p_z,   g_z);

    const int smem0 = (80  * G_ + 2 * 80  * INROWF_) * 4;  // 104960 B
    const int smem1 = (128 * G_ + 2 * 128 * INROWF_) * 4;  // 167936 B
    cudaFuncSetAttribute((const void*)lstm_kernel<80, 0>,
                         cudaFuncAttributeMaxDynamicSharedMemorySize, smem0);
    cudaFuncSetAttribute((const void*)lstm_kernel<128, 1>,
                         cudaFuncAttributeMaxDynamicSharedMemorySize, smem1);

    // features (N,F,T) -> (N,T,F)
    transpose_feat<<<N_, 256>>>(features, p_ft);

    // LSTM layer 0: g_ft -> g_h0 (blocked [t][blk][u][r])
    lstm_kernel<80, 0><<<N_ / 32, 512, smem0>>>(p_ft, p_h0, w_ih0, w_hh0, b_ih0, b_hh0);

    // dummy launch for profiler window alignment
    dummy_kernel<<<1, 32>>>(p_mu);

    // LSTM layer 1: g_h0 -> g_xs (channel 0)
    lstm_kernel<128, 1><<<N_ / 32, 512, smem1>>>(p_h0, p_xs, w_ih1, w_hh1, b_ih1, b_hh1);

    // adjacency
    stats_kernel<<<N_, 256>>>(p_xs, p_mu, p_sd);
    corr_kernel<<<dim3(N_ / 64, N_ / 64), 256>>>(p_xs, p_adj, p_mu, p_sd);
    rowsum_kernel<<<N_, 256>>>(p_adj, p_d);

    // GCN
    gemm_nn<1><<<dim3(HID_ / 64, N_ / 64), 256>>>(p_xs,  gc1_w, p_y, N_, HID_, T_,   p_d, nullptr);
    gemm_nn<2><<<dim3(HID_ / 64, N_ / 64), 256>>>(p_adj, p_y,   p_z, N_, HID_, N_,   p_d, gc1_b);
    gemm_nn<1><<<dim3(HID_ / 64, N_ / 64), 256>>>(p_z,   gc2_w, p_y, N_, HID_, HID_, p_d, nullptr);
    gemm_nn<2><<<dim3(HID_ / 64, N_ / 64), 256>>>(p_adj, p_y,   p_z, N_, HID_, N_,   p_d, gc2_b);

    // classifier
    clf_kernel<<<(N_ * NC_ + 255) / 256, 256>>>(p_z, clf_w, clf_b, out);
}